// round 16
// baseline (speedup 1.0000x reference)
#include <cuda_runtime.h>
#include <cuda_fp16.h>

#define N_NODES 100000
#define N_EDGES 1600000
#define N_GRAPHS 1024
#define HID 32
#define CAP 128
#define EPSN 1e-5f

#define GN_BLK 391   // ceil(100000/256)
#define GY_BLK 1250  // 100000*4 / 320 (exact)

static_assert((N_NODES * 8) % 256 == 0, "exact grid");
static_assert((N_NODES * 4) % 320 == 0, "exact grid ky");
static_assert(N_EDGES % 8 == 0, "edge vec8");

// ---------------- scratch (device globals; zero-initialized at load) --------
__device__ int    g_deg[N_NODES];
__device__ int    g_b32[N_NODES];
__device__ float  g_dinv[N_NODES];
__device__ float  g_cnt[N_GRAPHS];
__device__ __align__(16)  int   g_csr[(size_t)N_NODES * CAP];
__device__ __align__(128) uint2 g_hq[N_NODES * 8];   // hs = dinv*(x@W), fp16 x4
__device__ __align__(128) uint2 g_aq[N_NODES * 8];   // conv output, fp16 x4
__device__ __align__(128) uint2 g_xq[N_NODES * 8];   // activations x1/x2, fp16 x4
__device__ __align__(16) float g_gs[3][N_GRAPHS * HID];  // per-graph sums
__device__ __align__(16) float g_gv[3][N_GRAPHS * HID];  // per-graph sum-of-squares
__device__ __align__(16) float g_pool[N_GRAPHS * HID];   // pooling sums

// ---------------- helpers ---------------------------------------------------
__device__ __forceinline__ void f4fma(float4& a, float s, float4 v) {
    a.x += s * v.x; a.y += s * v.y; a.z += s * v.z; a.w += s * v.w;
}
__device__ __forceinline__ void f4add(float4& a, float4 v) {
    a.x += v.x; a.y += v.y; a.z += v.z; a.w += v.w;
}
__device__ __forceinline__ int clampN(int v) { return min(max(v, 0), N_NODES - 1); }

__device__ __forceinline__ float4 unpack_h(uint2 q) {
    __half2 lo = *(__half2*)&q.x, hi = *(__half2*)&q.y;
    float2 a = __half22float2(lo), b = __half22float2(hi);
    return make_float4(a.x, a.y, b.x, b.y);
}
__device__ __forceinline__ uint2 pack_h(float4 v) {
    __half2 lo = __floats2half2_rn(v.x, v.y);
    __half2 hi = __floats2half2_rn(v.z, v.w);
    uint2 q; q.x = *(unsigned*)&lo; q.y = *(unsigned*)&hi; return q;
}
__device__ __forceinline__ __half2 h2(unsigned u) { return *(__half2*)&u; }

__device__ __forceinline__ void redX(float4& v, int m) {
    v.x += __shfl_xor_sync(0xffffffffu, v.x, m);
    v.y += __shfl_xor_sync(0xffffffffu, v.y, m);
    v.z += __shfl_xor_sync(0xffffffffu, v.z, m);
    v.w += __shfl_xor_sync(0xffffffffu, v.w, m);
}
__device__ __forceinline__ void at4(float* p, float4 v) {
    atomicAdd(p + 0, v.x); atomicAdd(p + 1, v.y);
    atomicAdd(p + 2, v.z); atomicAdd(p + 3, v.w);
}

// Dual payload: lanes 0-7 flush A (sum), lanes 8-15 flush B (sumsq).
// (gather layout: 4 nodes x 8 f4 per warp)
__device__ __forceinline__ void seg_add2(float* baseA, float* baseB, int g,
                                         float4 va, float4 vb) {
    unsigned lane = threadIdx.x & 31u;
    int g0 = __shfl_sync(0xffffffffu, g, 0);
    if (__all_sync(0xffffffffu, g == g0)) {
        redX(va, 8); redX(va, 16);
        redX(vb, 8); redX(vb, 16);
        if (lane < 8)       at4(baseA + (size_t)g * HID + lane * 4, va);
        else if (lane < 16) at4(baseB + (size_t)g * HID + (lane - 8) * 4, vb);
    } else {
        unsigned f4 = lane & 7u;
        at4(baseA + (size_t)g * HID + f4 * 4, va);
        at4(baseB + (size_t)g * HID + f4 * 4, vb);
    }
}

// -------- edge pass: 8 edges/thread, 8 atomic chains in flight --------------
__global__ void k_edges(const int* __restrict__ ei) {
    int i = blockIdx.x * blockDim.x + threadIdx.x;
    int e = i * 8;
    if (e >= N_EDGES) return;
    int4 r0 = *(const int4*)(ei + e);
    int4 r1 = *(const int4*)(ei + e + 4);
    int4 c0 = *(const int4*)(ei + N_EDGES + e);
    int4 c1 = *(const int4*)(ei + N_EDGES + e + 4);
    int rr[8] = { r0.x, r0.y, r0.z, r0.w, r1.x, r1.y, r1.z, r1.w };
    int cc[8] = { c0.x, c0.y, c0.z, c0.w, c1.x, c1.y, c1.z, c1.w };
    int ss[8];
#pragma unroll
    for (int j = 0; j < 8; j++) {
        cc[j] = clampN(cc[j]);
        ss[j] = atomicAdd(&g_deg[cc[j]], 1);         // 8 independent ATOMGs
    }
#pragma unroll
    for (int j = 0; j < 8; j++) {
        if (ss[j] < CAP) g_csr[(size_t)cc[j] * CAP + ss[j]] = clampN(rr[j]);
    }
}

// batch decode + counts + dinv + layer-1 projection + pool zeroing, fused.
__global__ void k_bdh(const int* __restrict__ batch, const float* __restrict__ x,
                      const float* __restrict__ W) {
    __shared__ float sW[96];                         // W1: [3][32]
    if (threadIdx.x < 96) sW[threadIdx.x] = W[threadIdx.x];
    __syncthreads();
    int n = blockIdx.x * blockDim.x + threadIdx.x;
    for (int k = n; k < N_GRAPHS * HID; k += GN_BLK * 256) g_pool[k] = 0.0f;
    if (n >= N_NODES) return;
    int b = min(max(batch[n], 0), N_GRAPHS - 1);
    g_b32[n] = b;
    atomicAdd(&g_cnt[b], 1.0f);
    float di = rsqrtf((float)(g_deg[n] + 1));        // +1 self-loop
    g_dinv[n] = di;
    float x0 = x[n * 3 + 0] * di, x1 = x[n * 3 + 1] * di, x2 = x[n * 3 + 2] * di;
    uint2* dst = g_hq + n * 8;
#pragma unroll
    for (int q = 0; q < 8; q++) {
        float4 h;
        h.x = x0 * sW[q * 4 + 0] + x1 * sW[32 + q * 4 + 0] + x2 * sW[64 + q * 4 + 0];
        h.y = x0 * sW[q * 4 + 1] + x1 * sW[32 + q * 4 + 1] + x2 * sW[64 + q * 4 + 1];
        h.z = x0 * sW[q * 4 + 2] + x1 * sW[32 + q * 4 + 2] + x2 * sW[64 + q * 4 + 2];
        h.w = x0 * sW[q * 4 + 3] + x1 * sW[32 + q * 4 + 3] + x2 * sW[64 + q * 4 + 3];
        dst[q] = pack_h(h);
    }
}

// ------ GCN gather: 8 threads/node, 8-edge groups, dual index prefetch ------
// Per iteration: 8 independent message loads in flight + next 2 index quads.
__global__ void __launch_bounds__(256, 7)
k_gather(const float* __restrict__ bias, int L) {
    int t = blockIdx.x * 256 + threadIdx.x;          // exact grid: N*8
    int n = t >> 3, f4 = t & 7;
    float di = g_dinv[n];
    int d = min(g_deg[n], CAP);
    const int* cp = g_csr + (size_t)n * CAP;
    float4 acc = unpack_h(g_hq[t]);                  // self-loop term
    int e = 0;
    if (d >= 8) {
        int4 ra = *(const int4*)(cp);
        int4 rb = *(const int4*)(cp + 4);
        while (true) {
            int e2 = e + 8;
            bool more = (e2 + 8 <= d);
            int4 na, nb;
            if (more) {                              // prefetch next index quads
                na = *(const int4*)(cp + e2);
                nb = *(const int4*)(cp + e2 + 4);
            }
            uint2 q0 = g_hq[ra.x * 8 + f4];
            uint2 q1 = g_hq[ra.y * 8 + f4];
            uint2 q2 = g_hq[ra.z * 8 + f4];
            uint2 q3 = g_hq[ra.w * 8 + f4];
            uint2 q4 = g_hq[rb.x * 8 + f4];
            uint2 q5 = g_hq[rb.y * 8 + f4];
            uint2 q6 = g_hq[rb.z * 8 + f4];
            uint2 q7 = g_hq[rb.w * 8 + f4];
            __half2 slo = __hadd2(__hadd2(__hadd2(h2(q0.x), h2(q1.x)),
                                          __hadd2(h2(q2.x), h2(q3.x))),
                                  __hadd2(__hadd2(h2(q4.x), h2(q5.x)),
                                          __hadd2(h2(q6.x), h2(q7.x))));
            __half2 shi = __hadd2(__hadd2(__hadd2(h2(q0.y), h2(q1.y)),
                                          __hadd2(h2(q2.y), h2(q3.y))),
                                  __hadd2(__hadd2(h2(q4.y), h2(q5.y)),
                                          __hadd2(h2(q6.y), h2(q7.y))));
            float2 flo = __half22float2(slo);
            float2 fhi = __half22float2(shi);
            acc.x += flo.x; acc.y += flo.y; acc.z += fhi.x; acc.w += fhi.y;
            e = e2;
            if (!more) break;
            ra = na; rb = nb;
        }
    }
    if (e + 4 <= d) {                                // 4-wide tail
        int4 rr = *(const int4*)(cp + e);
        uint2 q0 = g_hq[rr.x * 8 + f4];
        uint2 q1 = g_hq[rr.y * 8 + f4];
        uint2 q2 = g_hq[rr.z * 8 + f4];
        uint2 q3 = g_hq[rr.w * 8 + f4];
        __half2 slo = __hadd2(__hadd2(h2(q0.x), h2(q1.x)),
                              __hadd2(h2(q2.x), h2(q3.x)));
        __half2 shi = __hadd2(__hadd2(h2(q0.y), h2(q1.y)),
                              __hadd2(h2(q2.y), h2(q3.y)));
        float2 flo = __half22float2(slo);
        float2 fhi = __half22float2(shi);
        acc.x += flo.x; acc.y += flo.y; acc.z += fhi.x; acc.w += fhi.y;
        e += 4;
    }
    for (; e < d; e++) f4add(acc, unpack_h(g_hq[cp[e] * 8 + f4]));
    float4 b4 = ((const float4*)bias)[f4];
    float4 out;
    out.x = b4.x + di * acc.x;
    out.y = b4.y + di * acc.y;
    out.z = b4.z + di * acc.z;
    out.w = b4.w + di * acc.w;
    g_aq[t] = pack_h(out);                           // fp16 conv output
    float4 sq = make_float4(out.x * out.x, out.y * out.y, out.z * out.z, out.w * out.w);
    seg_add2(g_gs[L], g_gv[L], g_b32[n], out, sq);   // fp32 mean + var sums
}

// ------- GraphNorm + residual + relu + {next x@W | pooling}, 2 nodes/thread -
// Warp = 8 nodes: lane p*8+f4 owns feature-quad f4 of nodes n0=base+2p, n0+1.
// NEXTW matmul: y broadcast via bank-skewed smem (2 STS + 16 LDS per thread).
template <int RES, int POOL, int NEXTW>
__global__ void __launch_bounds__(320, 6)
k_y(const float* __restrict__ w, const float* __restrict__ be,
    const float* __restrict__ ms, const float* __restrict__ Wn, int L) {
    __shared__ float4 sw[256];
    __shared__ float4 sy[10][2][40];                 // [warp][node-of-pair][skewed lane]
    int tid = threadIdx.x;                           // blockDim = 320
    if (NEXTW) {
        if (tid < 256) sw[tid] = ((const float4*)Wn)[tid];
        __syncthreads();
    }
    int i = blockIdx.x * 320 + tid;                  // exact: N*4 threads
    unsigned lane = tid & 31u;
    unsigned wid = (unsigned)tid >> 5;
    int f4 = lane & 7;
    int p  = lane >> 3;                              // node-pair slot 0..3
    int n0 = ((i >> 5) << 3) + (p << 1);
    int n1 = n0 + 1;

    float4 mv = ((const float4*)ms)[f4];
    float4 w4 = ((const float4*)w)[f4];
    float4 b4 = ((const float4*)be)[f4];

    int   gA = g_b32[n0],  gB = g_b32[n1];
    float rcA = 1.0f / fmaxf(g_cnt[gA], 1.0f);
    float rcB = 1.0f / fmaxf(g_cnt[gB], 1.0f);

    float4 y0, y1;
#pragma unroll
    for (int nn = 0; nn < 2; nn++) {
        int n = nn ? n1 : n0;
        int g = nn ? gB : gA;
        float rc = nn ? rcB : rcA;
        float4 S  = ((const float4*)(g_gs[L] + (size_t)g * HID))[f4];
        float4 SS = ((const float4*)(g_gv[L] + (size_t)g * HID))[f4];
        float4 a = unpack_h(g_aq[n * 8 + f4]);
        float4 y;
        float mean, s, var;
        mean = S.x * rc; s = mean * mv.x; var = SS.x * rc - 2.f * s * mean + s * s;
        y.x = w4.x * (a.x - s) * rsqrtf(var + EPSN) + b4.x;
        mean = S.y * rc; s = mean * mv.y; var = SS.y * rc - 2.f * s * mean + s * s;
        y.y = w4.y * (a.y - s) * rsqrtf(var + EPSN) + b4.y;
        mean = S.z * rc; s = mean * mv.z; var = SS.z * rc - 2.f * s * mean + s * s;
        y.z = w4.z * (a.z - s) * rsqrtf(var + EPSN) + b4.z;
        mean = S.w * rc; s = mean * mv.w; var = SS.w * rc - 2.f * s * mean + s * s;
        y.w = w4.w * (a.w - s) * rsqrtf(var + EPSN) + b4.w;
        if (RES) {
            float4 xo = unpack_h(g_xq[n * 8 + f4]);
            y.x += xo.x; y.y += xo.y; y.z += xo.z; y.w += xo.w;
        }
        y.x = fmaxf(y.x, 0.f); y.y = fmaxf(y.y, 0.f);
        y.z = fmaxf(y.z, 0.f); y.w = fmaxf(y.w, 0.f);
        if (nn) y1 = y; else y0 = y;
    }

    if (POOL) {
        int gf = __shfl_sync(0xffffffffu, gA, 0);
        if (__all_sync(0xffffffffu, (gA == gf) & (gB == gf))) {
            float4 v = make_float4(y0.x + y1.x, y0.y + y1.y, y0.z + y1.z, y0.w + y1.w);
            redX(v, 8); redX(v, 16);
            if (lane < 8) at4(g_pool + (size_t)gf * HID + lane * 4, v);
        } else {
            at4(g_pool + (size_t)gA * HID + f4 * 4, y0);
            at4(g_pool + (size_t)gB * HID + f4 * 4, y1);
        }
    } else {
        g_xq[n0 * 8 + f4] = pack_h(y0);
        g_xq[n1 * 8 + f4] = pack_h(y1);
    }

    if (NEXTW) {
        // h = dinv * (y @ Wn); y broadcast through bank-skewed smem
        unsigned sk = lane + (lane >> 3);            // skew: p-stride 9
        sy[wid][0][sk] = y0;
        sy[wid][1][sk] = y1;
        __syncwarp();
        float4 acc0 = make_float4(0.f, 0.f, 0.f, 0.f);
        float4 acc1 = make_float4(0.f, 0.f, 0.f, 0.f);
        unsigned srow = (unsigned)p * 9u;
#pragma unroll
        for (int j = 0; j < 8; j++) {
            float4 a0 = sy[wid][0][srow + j];        // broadcast within octet
            float4 a1 = sy[wid][1][srow + j];
            float4 w0 = sw[(j * 4 + 0) * 8 + f4];
            float4 w1 = sw[(j * 4 + 1) * 8 + f4];
            float4 w2 = sw[(j * 4 + 2) * 8 + f4];
            float4 w3 = sw[(j * 4 + 3) * 8 + f4];
            f4fma(acc0, a0.x, w0); f4fma(acc1, a1.x, w0);
            f4fma(acc0, a0.y, w1); f4fma(acc1, a1.y, w1);
            f4fma(acc0, a0.z, w2); f4fma(acc1, a1.z, w2);
            f4fma(acc0, a0.w, w3); f4fma(acc1, a1.w, w3);
        }
        float d0 = g_dinv[n0], d1 = g_dinv[n1];
        acc0.x *= d0; acc0.y *= d0; acc0.z *= d0; acc0.w *= d0;
        acc1.x *= d1; acc1.y *= d1; acc1.z *= d1; acc1.w *= d1;
        g_hq[n0 * 8 + f4] = pack_h(acc0);
        g_hq[n1 * 8 + f4] = pack_h(acc1);
    }
}

// ------- head + end-of-launch scratch re-zeroing ----------------------------
__global__ void k_final(const float* __restrict__ Wl, const float* __restrict__ bl,
                        float* __restrict__ out) {
    int i = blockIdx.x * blockDim.x + threadIdx.x;
    int g = i / 3, j = i - g * 3;
    if (i < N_GRAPHS * 3) {
        float rc = 1.0f / fmaxf(g_cnt[g], 1.0f);
        const float* pr = g_pool + (size_t)g * HID;
        float acc = bl[j];
#pragma unroll
        for (int f = 0; f < HID; f++) acc += pr[f] * rc * Wl[f * 3 + j];
        out[i] = acc;
    }
    __syncthreads();
    if (i < N_GRAPHS * 3 && j == 0) g_cnt[g] = 0.0f;
    for (int k = i; k < N_NODES; k += GN_BLK * 256) g_deg[k] = 0;
    for (int k = i; k < N_GRAPHS * HID; k += GN_BLK * 256) {
        g_gs[0][k] = 0.0f; g_gs[1][k] = 0.0f; g_gs[2][k] = 0.0f;
        g_gv[0][k] = 0.0f; g_gv[1][k] = 0.0f; g_gv[2][k] = 0.0f;
    }
}

// ---------------- launch -----------------------------------------------------
extern "C" void kernel_launch(void* const* d_in, const int* in_sizes, int n_in,
                              void* d_out, int out_size) {
    const float* x     = (const float*)d_in[0];
    const int*   ei    = (const int*)d_in[1];     // int32 (JAX x64 disabled)
    const int*   batch = (const int*)d_in[2];     // int32
    const float* W1 = (const float*)d_in[3];
    const float* b1 = (const float*)d_in[4];
    const float* W2 = (const float*)d_in[5];
    const float* b2 = (const float*)d_in[6];
    const float* W3 = (const float*)d_in[7];
    const float* b3 = (const float*)d_in[8];
    const float* g1 = (const float*)d_in[9];
    const float* be1 = (const float*)d_in[10];
    const float* ms1 = (const float*)d_in[11];
    const float* g2 = (const float*)d_in[12];
    const float* be2 = (const float*)d_in[13];
    const float* ms2 = (const float*)d_in[14];
    const float* g3 = (const float*)d_in[15];
    const float* be3 = (const float*)d_in[16];
    const float* ms3 = (const float*)d_in[17];
    const float* Wl = (const float*)d_in[18];
    const float* bl = (const float*)d_in[19];
    float* out = (float*)d_out;

    const int GE = (N_EDGES / 8 + 255) / 256;       // 782
    const int GF = (N_NODES * 8) / 256;             // 3125 (exact)

    k_edges<<<GE, 256>>>(ei);
    k_bdh<<<GN_BLK, 256>>>(batch, x, W1);

    k_gather<<<GF, 256>>>(b1, 0);
    k_y<0, 0, 1><<<GY_BLK, 320>>>(g1, be1, ms1, W2, 0); // gn+relu, emit h2

    k_gather<<<GF, 256>>>(b2, 1);
    k_y<1, 0, 1><<<GY_BLK, 320>>>(g2, be2, ms2, W3, 1); // gn+res+relu, emit h3

    k_gather<<<GF, 256>>>(b3, 2);
    k_y<1, 1, 0><<<GY_BLK, 320>>>(g3, be3, ms3, W3, 2); // gn+res+relu, pool

    k_final<<<GN_BLK, 256>>>(Wl, bl, out);
}

// round 17
// speedup vs baseline: 1.1688x; 1.1688x over previous
#include <cuda_runtime.h>
#include <cuda_fp16.h>

#define N_NODES 100000
#define N_EDGES 1600000
#define N_GRAPHS 1024
#define HID 32
#define CAP 128
#define EPSN 1e-5f

#define GN_BLK 391   // ceil(100000/256)
#define GY_BLK 1250  // 100000*4 / 320 (exact)

static_assert((N_NODES * 8) % 256 == 0, "exact grid");
static_assert((N_NODES * 4) % 320 == 0, "exact grid ky");
static_assert(N_EDGES % 4 == 0, "edge vec");

// ---------------- scratch (device globals; zero-initialized at load) --------
__device__ int    g_deg[N_NODES];
__device__ int    g_b32[N_NODES];
__device__ float  g_dinv[N_NODES];
__device__ float  g_cnt[N_GRAPHS];
__device__ __align__(16)  int   g_csr[(size_t)N_NODES * CAP];
__device__ __align__(128) uint2 g_hq[N_NODES * 8];   // hs = dinv*(x@W), fp16 x4
__device__ __align__(128) uint2 g_aq[N_NODES * 8];   // conv output, fp16 x4
__device__ __align__(128) uint2 g_xq[N_NODES * 8];   // activations x1/x2, fp16 x4
__device__ __align__(16) float g_gs[3][N_GRAPHS * HID];  // per-graph sums
__device__ __align__(16) float g_gv[3][N_GRAPHS * HID];  // per-graph sum-of-squares
__device__ __align__(16) float g_pool[N_GRAPHS * HID];   // pooling sums

// ---------------- helpers ---------------------------------------------------
__device__ __forceinline__ void f4fma(float4& a, float s, float4 v) {
    a.x += s * v.x; a.y += s * v.y; a.z += s * v.z; a.w += s * v.w;
}
__device__ __forceinline__ void f4add(float4& a, float4 v) {
    a.x += v.x; a.y += v.y; a.z += v.z; a.w += v.w;
}
__device__ __forceinline__ int clampN(int v) { return min(max(v, 0), N_NODES - 1); }

__device__ __forceinline__ float4 unpack_h(uint2 q) {
    __half2 lo = *(__half2*)&q.x, hi = *(__half2*)&q.y;
    float2 a = __half22float2(lo), b = __half22float2(hi);
    return make_float4(a.x, a.y, b.x, b.y);
}
__device__ __forceinline__ uint2 pack_h(float4 v) {
    __half2 lo = __floats2half2_rn(v.x, v.y);
    __half2 hi = __floats2half2_rn(v.z, v.w);
    uint2 q; q.x = *(unsigned*)&lo; q.y = *(unsigned*)&hi; return q;
}
__device__ __forceinline__ __half2 h2(unsigned u) { return *(__half2*)&u; }

__device__ __forceinline__ void redX(float4& v, int m) {
    v.x += __shfl_xor_sync(0xffffffffu, v.x, m);
    v.y += __shfl_xor_sync(0xffffffffu, v.y, m);
    v.z += __shfl_xor_sync(0xffffffffu, v.z, m);
    v.w += __shfl_xor_sync(0xffffffffu, v.w, m);
}
__device__ __forceinline__ void at4(float* p, float4 v) {
    atomicAdd(p + 0, v.x); atomicAdd(p + 1, v.y);
    atomicAdd(p + 2, v.z); atomicAdd(p + 3, v.w);
}

// Dual payload: lanes 0-7 flush A (sum), lanes 8-15 flush B (sumsq).
// (gather layout: 4 nodes x 8 f4 per warp)
__device__ __forceinline__ void seg_add2(float* baseA, float* baseB, int g,
                                         float4 va, float4 vb) {
    unsigned lane = threadIdx.x & 31u;
    int g0 = __shfl_sync(0xffffffffu, g, 0);
    if (__all_sync(0xffffffffu, g == g0)) {
        redX(va, 8); redX(va, 16);
        redX(vb, 8); redX(vb, 16);
        if (lane < 8)       at4(baseA + (size_t)g * HID + lane * 4, va);
        else if (lane < 16) at4(baseB + (size_t)g * HID + (lane - 8) * 4, vb);
    } else {
        unsigned f4 = lane & 7u;
        at4(baseA + (size_t)g * HID + f4 * 4, va);
        at4(baseB + (size_t)g * HID + f4 * 4, vb);
    }
}

// ---------------- edge pass (deg starts zeroed: module load / prev k_final) -
__global__ void k_edges(const int* __restrict__ ei) {
    int i = blockIdx.x * blockDim.x + threadIdx.x;
    int e = i * 4;
    if (e >= N_EDGES) return;
    int4 r = *(const int4*)(ei + e);
    int4 c = *(const int4*)(ei + N_EDGES + e);
#pragma unroll
    for (int j = 0; j < 4; j++) {
        int rr = clampN(j == 0 ? r.x : j == 1 ? r.y : j == 2 ? r.z : r.w);
        int cc = clampN(j == 0 ? c.x : j == 1 ? c.y : j == 2 ? c.z : c.w);
        int s = atomicAdd(&g_deg[cc], 1);
        if (s < CAP) g_csr[(size_t)cc * CAP + s] = rr;
    }
}

// batch decode + counts + dinv + layer-1 projection + pool zeroing, fused.
__global__ void k_bdh(const int* __restrict__ batch, const float* __restrict__ x,
                      const float* __restrict__ W) {
    __shared__ float sW[96];                         // W1: [3][32]
    if (threadIdx.x < 96) sW[threadIdx.x] = W[threadIdx.x];
    __syncthreads();
    int n = blockIdx.x * blockDim.x + threadIdx.x;
    for (int k = n; k < N_GRAPHS * HID; k += GN_BLK * 256) g_pool[k] = 0.0f;
    if (n >= N_NODES) return;
    int b = min(max(batch[n], 0), N_GRAPHS - 1);
    g_b32[n] = b;
    atomicAdd(&g_cnt[b], 1.0f);
    float di = rsqrtf((float)(g_deg[n] + 1));        // +1 self-loop
    g_dinv[n] = di;
    float x0 = x[n * 3 + 0] * di, x1 = x[n * 3 + 1] * di, x2 = x[n * 3 + 2] * di;
    uint2* dst = g_hq + n * 8;
#pragma unroll
    for (int q = 0; q < 8; q++) {
        float4 h;
        h.x = x0 * sW[q * 4 + 0] + x1 * sW[32 + q * 4 + 0] + x2 * sW[64 + q * 4 + 0];
        h.y = x0 * sW[q * 4 + 1] + x1 * sW[32 + q * 4 + 1] + x2 * sW[64 + q * 4 + 1];
        h.z = x0 * sW[q * 4 + 2] + x1 * sW[32 + q * 4 + 2] + x2 * sW[64 + q * 4 + 2];
        h.w = x0 * sW[q * 4 + 3] + x1 * sW[32 + q * 4 + 3] + x2 * sW[64 + q * 4 + 3];
        dst[q] = pack_h(h);
    }
}

// ------ GCN gather: 8 threads/node, 8-edge groups, dual index prefetch ------
// Per iteration: 8 independent message loads in flight + next 2 index quads.
// L templated: g_gs[L]/g_gv[L] bases fold to immediates.
template <int L>
__global__ void __launch_bounds__(256, 6)
k_gather(const float* __restrict__ bias) {
    int t = blockIdx.x * 256 + threadIdx.x;          // exact grid: N*8
    int n = t >> 3, f4 = t & 7;
    float di = g_dinv[n];
    int d = min(g_deg[n], CAP);
    const int* cp = g_csr + (size_t)n * CAP;
    float4 acc = unpack_h(g_hq[t]);                  // self-loop term
    int e = 0;
    if (d >= 8) {
        int4 ra = *(const int4*)(cp);
        int4 rb = *(const int4*)(cp + 4);
        while (true) {
            int e2 = e + 8;
            bool more = (e2 + 8 <= d);
            int4 na, nb;
            if (more) {                              // prefetch next index quads
                na = *(const int4*)(cp + e2);
                nb = *(const int4*)(cp + e2 + 4);
            }
            uint2 q0 = g_hq[ra.x * 8 + f4];
            uint2 q1 = g_hq[ra.y * 8 + f4];
            uint2 q2 = g_hq[ra.z * 8 + f4];
            uint2 q3 = g_hq[ra.w * 8 + f4];
            uint2 q4 = g_hq[rb.x * 8 + f4];
            uint2 q5 = g_hq[rb.y * 8 + f4];
            uint2 q6 = g_hq[rb.z * 8 + f4];
            uint2 q7 = g_hq[rb.w * 8 + f4];
            __half2 slo = __hadd2(__hadd2(__hadd2(h2(q0.x), h2(q1.x)),
                                          __hadd2(h2(q2.x), h2(q3.x))),
                                  __hadd2(__hadd2(h2(q4.x), h2(q5.x)),
                                          __hadd2(h2(q6.x), h2(q7.x))));
            __half2 shi = __hadd2(__hadd2(__hadd2(h2(q0.y), h2(q1.y)),
                                          __hadd2(h2(q2.y), h2(q3.y))),
                                  __hadd2(__hadd2(h2(q4.y), h2(q5.y)),
                                          __hadd2(h2(q6.y), h2(q7.y))));
            float2 flo = __half22float2(slo);
            float2 fhi = __half22float2(shi);
            acc.x += flo.x; acc.y += flo.y; acc.z += fhi.x; acc.w += fhi.y;
            e = e2;
            if (!more) break;
            ra = na; rb = nb;
        }
    }
    if (e + 4 <= d) {                                // 4-wide tail
        int4 rr = *(const int4*)(cp + e);
        uint2 q0 = g_hq[rr.x * 8 + f4];
        uint2 q1 = g_hq[rr.y * 8 + f4];
        uint2 q2 = g_hq[rr.z * 8 + f4];
        uint2 q3 = g_hq[rr.w * 8 + f4];
        __half2 slo = __hadd2(__hadd2(h2(q0.x), h2(q1.x)),
                              __hadd2(h2(q2.x), h2(q3.x)));
        __half2 shi = __hadd2(__hadd2(h2(q0.y), h2(q1.y)),
                              __hadd2(h2(q2.y), h2(q3.y)));
        float2 flo = __half22float2(slo);
        float2 fhi = __half22float2(shi);
        acc.x += flo.x; acc.y += flo.y; acc.z += fhi.x; acc.w += fhi.y;
        e += 4;
    }
    for (; e < d; e++) f4add(acc, unpack_h(g_hq[cp[e] * 8 + f4]));
    float4 b4 = ((const float4*)bias)[f4];
    float4 out;
    out.x = b4.x + di * acc.x;
    out.y = b4.y + di * acc.y;
    out.z = b4.z + di * acc.z;
    out.w = b4.w + di * acc.w;
    g_aq[t] = pack_h(out);                           // fp16 conv output
    float4 sq = make_float4(out.x * out.x, out.y * out.y, out.z * out.z, out.w * out.w);
    seg_add2(g_gs[L], g_gv[L], g_b32[n], out, sq);   // fp32 mean + var sums
}

// ------- GraphNorm + residual + relu + {next x@W | pooling}, 2 nodes/thread -
// Warp = 8 nodes: lane p*8+f4 owns feature-quad f4 of nodes n0=base+2p, n0+1.
// NEXTW matmul: y broadcast via bank-skewed smem (2 STS + 16 LDS per thread).
template <int RES, int POOL, int NEXTW, int L>
__global__ void __launch_bounds__(320, 6)
k_y(const float* __restrict__ w, const float* __restrict__ be,
    const float* __restrict__ ms, const float* __restrict__ Wn) {
    __shared__ float4 sw[256];
    __shared__ float4 sy[10][2][40];                 // [warp][node-of-pair][skewed lane]
    int tid = threadIdx.x;                           // blockDim = 320
    if (NEXTW) {
        if (tid < 256) sw[tid] = ((const float4*)Wn)[tid];
        __syncthreads();
    }
    int i = blockIdx.x * 320 + tid;                  // exact: N*4 threads
    unsigned lane = tid & 31u;
    unsigned wid = (unsigned)tid >> 5;
    int f4 = lane & 7;
    int p  = lane >> 3;                              // node-pair slot 0..3
    int n0 = ((i >> 5) << 3) + (p << 1);
    int n1 = n0 + 1;

    float4 mv = ((const float4*)ms)[f4];
    float4 w4 = ((const float4*)w)[f4];
    float4 b4 = ((const float4*)be)[f4];

    int   gA = g_b32[n0],  gB = g_b32[n1];
    float rcA = 1.0f / fmaxf(g_cnt[gA], 1.0f);
    float rcB = 1.0f / fmaxf(g_cnt[gB], 1.0f);

    float4 y0, y1;
#pragma unroll
    for (int nn = 0; nn < 2; nn++) {
        int n = nn ? n1 : n0;
        int g = nn ? gB : gA;
        float rc = nn ? rcB : rcA;
        float4 S  = ((const float4*)(g_gs[L] + (size_t)g * HID))[f4];
        float4 SS = ((const float4*)(g_gv[L] + (size_t)g * HID))[f4];
        float4 a = unpack_h(g_aq[n * 8 + f4]);
        float4 y;
        float mean, s, var;
        mean = S.x * rc; s = mean * mv.x; var = SS.x * rc - 2.f * s * mean + s * s;
        y.x = w4.x * (a.x - s) * rsqrtf(var + EPSN) + b4.x;
        mean = S.y * rc; s = mean * mv.y; var = SS.y * rc - 2.f * s * mean + s * s;
        y.y = w4.y * (a.y - s) * rsqrtf(var + EPSN) + b4.y;
        mean = S.z * rc; s = mean * mv.z; var = SS.z * rc - 2.f * s * mean + s * s;
        y.z = w4.z * (a.z - s) * rsqrtf(var + EPSN) + b4.z;
        mean = S.w * rc; s = mean * mv.w; var = SS.w * rc - 2.f * s * mean + s * s;
        y.w = w4.w * (a.w - s) * rsqrtf(var + EPSN) + b4.w;
        if (RES) {
            float4 xo = unpack_h(g_xq[n * 8 + f4]);
            y.x += xo.x; y.y += xo.y; y.z += xo.z; y.w += xo.w;
        }
        y.x = fmaxf(y.x, 0.f); y.y = fmaxf(y.y, 0.f);
        y.z = fmaxf(y.z, 0.f); y.w = fmaxf(y.w, 0.f);
        if (nn) y1 = y; else y0 = y;
    }

    if (POOL) {
        int gf = __shfl_sync(0xffffffffu, gA, 0);
        if (__all_sync(0xffffffffu, (gA == gf) & (gB == gf))) {
            float4 v = make_float4(y0.x + y1.x, y0.y + y1.y, y0.z + y1.z, y0.w + y1.w);
            redX(v, 8); redX(v, 16);
            if (lane < 8) at4(g_pool + (size_t)gf * HID + lane * 4, v);
        } else {
            at4(g_pool + (size_t)gA * HID + f4 * 4, y0);
            at4(g_pool + (size_t)gB * HID + f4 * 4, y1);
        }
    } else {
        g_xq[n0 * 8 + f4] = pack_h(y0);
        g_xq[n1 * 8 + f4] = pack_h(y1);
    }

    if (NEXTW) {
        // h = dinv * (y @ Wn); y broadcast through bank-skewed smem
        unsigned sk = lane + (lane >> 3);            // skew: p-stride 9
        sy[wid][0][sk] = y0;
        sy[wid][1][sk] = y1;
        __syncwarp();
        float4 acc0 = make_float4(0.f, 0.f, 0.f, 0.f);
        float4 acc1 = make_float4(0.f, 0.f, 0.f, 0.f);
        unsigned srow = (unsigned)p * 9u;
#pragma unroll
        for (int j = 0; j < 8; j++) {
            float4 a0 = sy[wid][0][srow + j];        // broadcast within octet
            float4 a1 = sy[wid][1][srow + j];
            float4 w0 = sw[(j * 4 + 0) * 8 + f4];
            float4 w1 = sw[(j * 4 + 1) * 8 + f4];
            float4 w2 = sw[(j * 4 + 2) * 8 + f4];
            float4 w3 = sw[(j * 4 + 3) * 8 + f4];
            f4fma(acc0, a0.x, w0); f4fma(acc1, a1.x, w0);
            f4fma(acc0, a0.y, w1); f4fma(acc1, a1.y, w1);
            f4fma(acc0, a0.z, w2); f4fma(acc1, a1.z, w2);
            f4fma(acc0, a0.w, w3); f4fma(acc1, a1.w, w3);
        }
        float d0 = g_dinv[n0], d1 = g_dinv[n1];
        acc0.x *= d0; acc0.y *= d0; acc0.z *= d0; acc0.w *= d0;
        acc1.x *= d1; acc1.y *= d1; acc1.z *= d1; acc1.w *= d1;
        g_hq[n0 * 8 + f4] = pack_h(acc0);
        g_hq[n1 * 8 + f4] = pack_h(acc1);
    }
}

// ------- head + end-of-launch scratch re-zeroing ----------------------------
__global__ void k_final(const float* __restrict__ Wl, const float* __restrict__ bl,
                        float* __restrict__ out) {
    int i = blockIdx.x * blockDim.x + threadIdx.x;
    int g = i / 3, j = i - g * 3;
    if (i < N_GRAPHS * 3) {
        float rc = 1.0f / fmaxf(g_cnt[g], 1.0f);
        const float* pr = g_pool + (size_t)g * HID;
        float acc = bl[j];
#pragma unroll
        for (int f = 0; f < HID; f++) acc += pr[f] * rc * Wl[f * 3 + j];
        out[i] = acc;
    }
    __syncthreads();
    if (i < N_GRAPHS * 3 && j == 0) g_cnt[g] = 0.0f;
    for (int k = i; k < N_NODES; k += GN_BLK * 256) g_deg[k] = 0;
    for (int k = i; k < N_GRAPHS * HID; k += GN_BLK * 256) {
        g_gs[0][k] = 0.0f; g_gs[1][k] = 0.0f; g_gs[2][k] = 0.0f;
        g_gv[0][k] = 0.0f; g_gv[1][k] = 0.0f; g_gv[2][k] = 0.0f;
    }
}

// ---------------- launch -----------------------------------------------------
extern "C" void kernel_launch(void* const* d_in, const int* in_sizes, int n_in,
                              void* d_out, int out_size) {
    const float* x     = (const float*)d_in[0];
    const int*   ei    = (const int*)d_in[1];     // int32 (JAX x64 disabled)
    const int*   batch = (const int*)d_in[2];     // int32
    const float* W1 = (const float*)d_in[3];
    const float* b1 = (const float*)d_in[4];
    const float* W2 = (const float*)d_in[5];
    const float* b2 = (const float*)d_in[6];
    const float* W3 = (const float*)d_in[7];
    const float* b3 = (const float*)d_in[8];
    const float* g1 = (const float*)d_in[9];
    const float* be1 = (const float*)d_in[10];
    const float* ms1 = (const float*)d_in[11];
    const float* g2 = (const float*)d_in[12];
    const float* be2 = (const float*)d_in[13];
    const float* ms2 = (const float*)d_in[14];
    const float* g3 = (const float*)d_in[15];
    const float* be3 = (const float*)d_in[16];
    const float* ms3 = (const float*)d_in[17];
    const float* Wl = (const float*)d_in[18];
    const float* bl = (const float*)d_in[19];
    float* out = (float*)d_out;

    const int GE = (N_EDGES / 4 + 255) / 256;       // 1563
    const int GF = (N_NODES * 8) / 256;             // 3125 (exact)

    k_edges<<<GE, 256>>>(ei);
    k_bdh<<<GN_BLK, 256>>>(batch, x, W1);

    k_gather<0><<<GF, 256>>>(b1);
    k_y<0, 0, 1, 0><<<GY_BLK, 320>>>(g1, be1, ms1, W2); // gn+relu, emit h2

    k_gather<1><<<GF, 256>>>(b2);
    k_y<1, 0, 1, 1><<<GY_BLK, 320>>>(g2, be2, ms2, W3); // gn+res+relu, emit h3

    k_gather<2><<<GF, 256>>>(b3);
    k_y<1, 1, 0, 2><<<GY_BLK, 320>>>(g3, be3, ms3, W3); // gn+res+relu, pool

    k_final<<<GN_BLK, 256>>>(Wl, bl, out);
}